// round 4
// baseline (speedup 1.0000x reference)
#include <cuda_runtime.h>
#include <cuda_bf16.h>
#include <cstdint>

#define B_ 32
#define L_ 1024
#define D_ 64

typedef __nv_bfloat16 bf16;

// bf16 hi/lo splits of enc and energy, [b][row][e] (e contiguous, 128B rows)
__device__ __align__(16) bf16 g_enc_hi[B_ * L_ * D_];
__device__ __align__(16) bf16 g_enc_lo[B_ * L_ * D_];
__device__ __align__(16) bf16 g_egy_hi[B_ * L_ * D_];
__device__ __align__(16) bf16 g_egy_lo[B_ * L_ * D_];

// ---------------------------------------------------------------------------
// helpers
// ---------------------------------------------------------------------------
__device__ __forceinline__ uint32_t smem_u32(const void* p) {
    uint32_t a;
    asm("{ .reg .u64 t; cvta.to.shared.u64 t, %1; cvt.u32.u64 %0, t; }"
        : "=r"(a) : "l"(p));
    return a;
}
__device__ __forceinline__ void cp16(void* dst_smem, const void* src) {
    uint32_t s = smem_u32(dst_smem);
    asm volatile("cp.async.cg.shared.global [%0], [%1], 16;" :: "r"(s), "l"(src));
}
__device__ __forceinline__ void cp_commit() { asm volatile("cp.async.commit_group;"); }
template <int N>
__device__ __forceinline__ void cp_wait() {
    asm volatile("cp.async.wait_group %0;" :: "n"(N));
}

__device__ __forceinline__ void ldsm_x4(uint32_t addr, uint32_t r[4]) {
    asm volatile("ldmatrix.sync.aligned.m8n8.x4.shared.b16 {%0,%1,%2,%3}, [%4];"
                 : "=r"(r[0]), "=r"(r[1]), "=r"(r[2]), "=r"(r[3]) : "r"(addr));
}
__device__ __forceinline__ void mma16816(float c[4], const uint32_t a[4],
                                         const uint32_t b0, const uint32_t b1) {
    asm volatile(
        "mma.sync.aligned.m16n8k16.row.col.f32.bf16.bf16.f32 "
        "{%0,%1,%2,%3}, {%4,%5,%6,%7}, {%8,%9}, {%0,%1,%2,%3};"
        : "+f"(c[0]), "+f"(c[1]), "+f"(c[2]), "+f"(c[3])
        : "r"(a[0]), "r"(a[1]), "r"(a[2]), "r"(a[3]), "r"(b0), "r"(b1));
}

// SW128 swizzle for 128B rows
__device__ __forceinline__ uint32_t swz(uint32_t o) { return o ^ ((o >> 3) & 0x70); }

__device__ __forceinline__ void split2(float a, float b, uint32_t& h, uint32_t& l) {
    bf16 ha = __float2bfloat16_rn(a), hb = __float2bfloat16_rn(b);
    bf16 la = __float2bfloat16_rn(a - __bfloat162float(ha));
    bf16 lb = __float2bfloat16_rn(b - __bfloat162float(hb));
    __nv_bfloat162 hh = __halves2bfloat162(ha, hb);
    __nv_bfloat162 ll = __halves2bfloat162(la, lb);
    h = *reinterpret_cast<uint32_t*>(&hh);
    l = *reinterpret_cast<uint32_t*>(&ll);
}

// ---------------------------------------------------------------------------
// Kernel 0: split enc -> bf16 hi/lo
// ---------------------------------------------------------------------------
__global__ __launch_bounds__(256) void split_enc_kernel(const float* __restrict__ enc) {
    const int n4 = B_ * L_ * D_ / 4;
    const float4* e4 = reinterpret_cast<const float4*>(enc);
    uint2* oh = reinterpret_cast<uint2*>(g_enc_hi);
    uint2* ol = reinterpret_cast<uint2*>(g_enc_lo);
    for (int i = blockIdx.x * 256 + threadIdx.x; i < n4; i += gridDim.x * 256) {
        float4 v = e4[i];
        uint2 h, l;
        split2(v.x, v.y, h.x, l.x);
        split2(v.z, v.w, h.y, l.y);
        oh[i] = h; ol[i] = l;
    }
}

// ---------------------------------------------------------------------------
// Kernel 1: energy[b][j][e] = sum_d enc[b][j][d]*W[e][d] + bias[e] -> bf16 hi/lo
// grid (8 j-blocks, 32 b), 256 threads
// ---------------------------------------------------------------------------
__global__ __launch_bounds__(256) void energy_kernel(
    const float* __restrict__ enc, const float* __restrict__ W,
    const float* __restrict__ bias) {
    __shared__ float Wt[D_][D_];     // [d][e]
    __shared__ float encs[D_][128];  // [d][j]; reused as enT[e][j]
    const int b = blockIdx.y, jb = blockIdx.x;
    const int tid = threadIdx.x;

    const float4* W4 = reinterpret_cast<const float4*>(W);
#pragma unroll
    for (int i = 0; i < 4; i++) {
        int f = tid + i * 256;
        int e = f >> 4, dq = f & 15;
        float4 w = W4[f];
        Wt[dq * 4 + 0][e] = w.x; Wt[dq * 4 + 1][e] = w.y;
        Wt[dq * 4 + 2][e] = w.z; Wt[dq * 4 + 3][e] = w.w;
    }
    const float4* enc4 =
        reinterpret_cast<const float4*>(enc + ((size_t)b * L_ + (size_t)jb * 128) * D_);
#pragma unroll
    for (int i = 0; i < 8; i++) {
        int f = tid + i * 256;
        int j = f >> 4, dq = f & 15;
        float4 v = enc4[f];
        encs[dq * 4 + 0][j] = v.x; encs[dq * 4 + 1][j] = v.y;
        encs[dq * 4 + 2][j] = v.z; encs[dq * 4 + 3][j] = v.w;
    }
    __syncthreads();

    const int w = tid >> 5, lane = tid & 31;
    const int e0 = w * 8;
    float acc[8][4];
#pragma unroll
    for (int e = 0; e < 8; e++)
#pragma unroll
        for (int q = 0; q < 4; q++) acc[e][q] = 0.f;
#pragma unroll 4
    for (int d = 0; d < D_; d++) {
        float4 ev = *reinterpret_cast<const float4*>(&encs[d][lane * 4]);
        float4 wa = *reinterpret_cast<const float4*>(&Wt[d][e0]);
        float4 wb = *reinterpret_cast<const float4*>(&Wt[d][e0 + 4]);
        float wv[8] = {wa.x, wa.y, wa.z, wa.w, wb.x, wb.y, wb.z, wb.w};
#pragma unroll
        for (int e = 0; e < 8; e++) {
            acc[e][0] = fmaf(wv[e], ev.x, acc[e][0]);
            acc[e][1] = fmaf(wv[e], ev.y, acc[e][1]);
            acc[e][2] = fmaf(wv[e], ev.z, acc[e][2]);
            acc[e][3] = fmaf(wv[e], ev.w, acc[e][3]);
        }
    }
    __syncthreads();   // done reading encs as [d][j]
#pragma unroll
    for (int e = 0; e < 8; e++) {
        float bb = bias[e0 + e];
        float4 o = make_float4(acc[e][0] + bb, acc[e][1] + bb,
                               acc[e][2] + bb, acc[e][3] + bb);
        *reinterpret_cast<float4*>(&encs[e0 + e][lane * 4]) = o;  // enT[e][j]
    }
    __syncthreads();

    // emit bf16 hi/lo, layout [j][e]
    const int j = tid >> 1, eh = (tid & 1) * 32;
    const size_t row = (size_t)b * L_ + jb * 128 + j;
    uint32_t hp[16], lp[16];
#pragma unroll
    for (int k = 0; k < 16; k++) {
        float v0 = encs[eh + 2 * k][j];
        float v1 = encs[eh + 2 * k + 1][j];
        split2(v0, v1, hp[k], lp[k]);
    }
    uint4* dh = reinterpret_cast<uint4*>(g_egy_hi + row * D_ + eh);
    uint4* dl = reinterpret_cast<uint4*>(g_egy_lo + row * D_ + eh);
#pragma unroll
    for (int q = 0; q < 4; q++) {
        dh[q] = make_uint4(hp[4 * q], hp[4 * q + 1], hp[4 * q + 2], hp[4 * q + 3]);
        dl[q] = make_uint4(lp[4 * q], lp[4 * q + 1], lp[4 * q + 2], lp[4 * q + 3]);
    }
}

// ---------------------------------------------------------------------------
// Kernel 2: scores via mma.sync bf16-split x3 + diag-zero + softmax + store.
// grid (32 tb, 32 b), 256 threads. CTA tile: 32 t x 1024 j.
// warp w -> mb = w>>2 (m16 block), ng = w&3 (n64 group within each 256-j slab)
// acc[slab 4][n8-tile 8][4] = 128 f32/thread.
// B (energy) streamed in 4 slabs of 256 j-rows (hi+lo = 64KB), double-buffered.
// ---------------------------------------------------------------------------
#define A_HI 0
#define A_LO 4096
#define BB   8192
#define BUFSZ 65536
#define SUMS_OFF (BB + 2 * BUFSZ)
#define SMEM_TOTAL (SUMS_OFF + 4 * 32 * 4)

__global__ __launch_bounds__(256, 1) void scores_mma_kernel(float* __restrict__ out) {
    extern __shared__ char smem[];
    const uint32_t sb = smem_u32(smem);
    float* sums = reinterpret_cast<float*>(smem + SUMS_OFF);  // [4 ng][32 rows]

    const int tid = threadIdx.x, w = tid >> 5, lane = tid & 31;
    const int b = blockIdx.y, tb = blockIdx.x, t0 = tb * 32;
    const int mb = w >> 2, ng = w & 3, g = lane >> 2, qc = lane & 3;

    // ---- A tile: enc hi/lo rows t0..t0+31 (swizzled) ----
    {
        const bf16* srh = g_enc_hi + ((size_t)b * L_ + t0) * D_;
        const bf16* srl = g_enc_lo + ((size_t)b * L_ + t0) * D_;
#pragma unroll
        for (int i = 0; i < 2; i++) {
            int idx = tid + i * 256;            // 512 chunks: 2 splits x 32 rows x 8
            int split = idx >> 8, rem = idx & 255, row = rem >> 3, c = rem & 7;
            const uint4 v = reinterpret_cast<const uint4*>(
                (split ? srl : srh) + row * D_)[c];
            *reinterpret_cast<uint4*>(
                smem + (split ? A_LO : A_HI) + swz(row * 128 + c * 16)) = v;
        }
    }

    // ---- prefetch B slabs 0,1 ----
    const bf16* bhb = g_egy_hi + (size_t)b * L_ * D_;
    const bf16* blb = g_egy_lo + (size_t)b * L_ * D_;
    auto load_slab = [&](int s, int buf) {
        const bf16* sh = bhb + (size_t)s * 256 * D_;
        const bf16* sl = blb + (size_t)s * 256 * D_;
        char* dst = smem + BB + buf * BUFSZ;
#pragma unroll
        for (int i = 0; i < 16; i++) {
            int idx = tid + i * 256;            // 4096: 2 splits x 256 rows x 8
            int split = idx >> 11, rem = idx & 2047, row = rem >> 3, c = rem & 7;
            cp16(dst + split * 32768 + swz(row * 128 + c * 16),
                 reinterpret_cast<const char*>(split ? sl : sh) + row * 128 + c * 16);
        }
    };
    load_slab(0, 0); cp_commit();
    load_slab(1, 1); cp_commit();

    float acc[4][8][4];
#pragma unroll
    for (int s = 0; s < 4; s++)
#pragma unroll
        for (int nt = 0; nt < 8; nt++)
#pragma unroll
            for (int q = 0; q < 4; q++) acc[s][nt][q] = 0.f;

    // A ldmatrix address (per kstep/split): row = mb*16 + (lane&15),
    // koff = kstep*16 + (lane>>4)*8
    const uint32_t a_row = (uint32_t)(mb * 16 + (lane & 15));
    const uint32_t a_kbase = (uint32_t)((lane >> 4) * 8);
    // B ldmatrix address: row = n0 + ((lane>>4)&1)*8 + (lane&7),
    // koff = kstep*16 + ((lane>>3)&1)*8
    const uint32_t b_rowoff = (uint32_t)(((lane >> 4) & 1) * 8 + (lane & 7));
    const uint32_t b_kbase = (uint32_t)(((lane >> 3) & 1) * 8);

#pragma unroll 1
    for (int s = 0; s < 4; s++) {
        cp_wait<1>();
        __syncthreads();
        const int buf = s & 1;
        const uint32_t bbase = sb + BB + buf * BUFSZ;
#pragma unroll
        for (int ks = 0; ks < 4; ks++) {
            uint32_t ah[4], al[4];
            const uint32_t a_off = swz(a_row * 128 + (a_kbase + ks * 16) * 2);
            ldsm_x4(sb + A_HI + a_off, ah);
            ldsm_x4(sb + A_LO + a_off, al);
#pragma unroll
            for (int p = 0; p < 4; p++) {       // nt pair p -> tiles 2p, 2p+1
                const uint32_t n0 = (uint32_t)(ng * 64 + p * 16);
                const uint32_t b_off =
                    swz((n0 + b_rowoff) * 128 + (b_kbase + ks * 16) * 2);
                uint32_t bh[4], bl[4];
                ldsm_x4(bbase + b_off, bh);
                ldsm_x4(bbase + 32768 + b_off, bl);
                mma16816(acc[s][2 * p],     ah, bh[0], bh[1]);
                mma16816(acc[s][2 * p + 1], ah, bh[2], bh[3]);
                mma16816(acc[s][2 * p],     al, bh[0], bh[1]);
                mma16816(acc[s][2 * p + 1], al, bh[2], bh[3]);
                mma16816(acc[s][2 * p],     ah, bl[0], bl[1]);
                mma16816(acc[s][2 * p + 1], ah, bl[2], bl[3]);
            }
        }
        __syncthreads();
        if (s + 2 < 4) load_slab(s + 2, buf);
        cp_commit();
    }

    // ---- epilogue: diag zero, exp in place, row sums ----
    const int r0 = t0 + mb * 16 + g;    // rows for c0,c1
    const int r1 = r0 + 8;              // rows for c2,c3
    float s0 = 0.f, s1 = 0.f;
#pragma unroll
    for (int s = 0; s < 4; s++)
#pragma unroll
        for (int nt = 0; nt < 8; nt++) {
            const int j = s * 256 + ng * 64 + nt * 8 + qc * 2;
            float* a = acc[s][nt];
            float v0 = (j == r0) ? 0.f : a[0];
            float v1 = (j + 1 == r0) ? 0.f : a[1];
            float v2 = (j == r1) ? 0.f : a[2];
            float v3 = (j + 1 == r1) ? 0.f : a[3];
            v0 = __expf(v0); v1 = __expf(v1); v2 = __expf(v2); v3 = __expf(v3);
            a[0] = v0; a[1] = v1; a[2] = v2; a[3] = v3;
            s0 += v0 + v1; s1 += v2 + v3;
        }
#pragma unroll
    for (int o = 1; o < 4; o <<= 1) {
        s0 += __shfl_xor_sync(0xffffffffu, s0, o);
        s1 += __shfl_xor_sync(0xffffffffu, s1, o);
    }
    if (qc == 0) {
        sums[ng * 32 + mb * 16 + g] = s0;
        sums[ng * 32 + mb * 16 + g + 8] = s1;
    }
    __syncthreads();
    const int lr0 = mb * 16 + g, lr1 = lr0 + 8;
    const float rinv0 =
        1.0f / (sums[lr0] + sums[32 + lr0] + sums[64 + lr0] + sums[96 + lr0]);
    const float rinv1 =
        1.0f / (sums[lr1] + sums[32 + lr1] + sums[64 + lr1] + sums[96 + lr1]);

    // ---- normalize + store ----
    float* out0 = out + (((size_t)r0 * B_ + b) << 10);
    float* out1 = out + (((size_t)r1 * B_ + b) << 10);
#pragma unroll
    for (int s = 0; s < 4; s++)
#pragma unroll
        for (int nt = 0; nt < 8; nt++) {
            const int j = s * 256 + ng * 64 + nt * 8 + qc * 2;
            float* a = acc[s][nt];
            *reinterpret_cast<float2*>(out0 + j) =
                make_float2(a[0] * rinv0, a[1] * rinv0);
            *reinterpret_cast<float2*>(out1 + j) =
                make_float2(a[2] * rinv1, a[3] * rinv1);
        }
}

// ---------------------------------------------------------------------------
extern "C" void kernel_launch(void* const* d_in, const int* in_sizes, int n_in,
                              void* d_out, int out_size) {
    (void)in_sizes; (void)n_in; (void)out_size;
    const float* enc  = (const float*)d_in[0];
    const float* W    = (const float*)d_in[1];
    const float* bias = (const float*)d_in[2];
    float* out = (float*)d_out;

    static int configured = 0;
    if (!configured) {
        cudaFuncSetAttribute(scores_mma_kernel,
                             cudaFuncAttributeMaxDynamicSharedMemorySize, SMEM_TOTAL);
        configured = 1;
    }

    split_enc_kernel<<<512, 256>>>(enc);
    energy_kernel<<<dim3(8, 32), 256>>>(enc, W, bias);
    scores_mma_kernel<<<dim3(32, 32), 256, SMEM_TOTAL>>>(out);
}

// round 5
// speedup vs baseline: 1.1253x; 1.1253x over previous
#include <cuda_runtime.h>
#include <cstdint>

#define B_ 32
#define L_ 1024
#define D_ 64
#define SLAB_K 8
#define NSLAB (D_ / SLAB_K)

// scratch: energyT[b][e][j]  (e is the GEMM-K dim of the scores GEMM)
__device__ float g_energyT[B_ * D_ * L_];

// packed fp32x2 FMA: d = a*b + d   (sm_103a FFMA2 — only reachable via PTX)
__device__ __forceinline__ void ffma2(float2& d, const float2 a, const float2 b) {
    asm("fma.rn.f32x2 %0, %1, %2, %0;"
        : "+l"(reinterpret_cast<unsigned long long&>(d))
        : "l"(reinterpret_cast<const unsigned long long&>(a)),
          "l"(reinterpret_cast<const unsigned long long&>(b)));
}

__device__ __forceinline__ void cp16(float* dst_smem, const float* src) {
    unsigned s = (unsigned)__cvta_generic_to_shared(dst_smem);
    asm volatile("cp.async.cg.shared.global [%0], [%1], 16;\n" :: "r"(s), "l"(src));
}
__device__ __forceinline__ void cp_commit() { asm volatile("cp.async.commit_group;\n"); }
template <int N>
__device__ __forceinline__ void cp_wait() {
    asm volatile("cp.async.wait_group %0;\n" :: "n"(N));
}

// ---------------------------------------------------------------------------
// Kernel 1: energyT[b][e][j] = sum_d enc[b][j][d] * W[e][d] + bias[e]
// grid (8 j-blocks, 32 b), 256 threads
// ---------------------------------------------------------------------------
__global__ __launch_bounds__(256) void energy_kernel(
    const float* __restrict__ enc, const float* __restrict__ W,
    const float* __restrict__ bias) {
    __shared__ float Wt[D_][D_];     // [d][e]
    __shared__ float encs[D_][128];  // [d][j]
    const int b = blockIdx.y, jb = blockIdx.x;
    const int tid = threadIdx.x;

    const float4* W4 = reinterpret_cast<const float4*>(W);
#pragma unroll
    for (int i = 0; i < 4; i++) {
        int f = tid + i * 256;
        int e = f >> 4, dq = f & 15;
        float4 w = W4[f];
        Wt[dq * 4 + 0][e] = w.x; Wt[dq * 4 + 1][e] = w.y;
        Wt[dq * 4 + 2][e] = w.z; Wt[dq * 4 + 3][e] = w.w;
    }
    const float4* enc4 =
        reinterpret_cast<const float4*>(enc + ((size_t)b * L_ + (size_t)jb * 128) * D_);
#pragma unroll
    for (int i = 0; i < 8; i++) {
        int f = tid + i * 256;
        int j = f >> 4, dq = f & 15;
        float4 v = enc4[f];
        encs[dq * 4 + 0][j] = v.x; encs[dq * 4 + 1][j] = v.y;
        encs[dq * 4 + 2][j] = v.z; encs[dq * 4 + 3][j] = v.w;
    }
    __syncthreads();

    const int w = tid >> 5, lane = tid & 31;
    const int e0 = w * 8;
    float2 acc[8][2];
#pragma unroll
    for (int e = 0; e < 8; e++) {
        acc[e][0] = make_float2(0.f, 0.f);
        acc[e][1] = make_float2(0.f, 0.f);
    }
#pragma unroll 4
    for (int d = 0; d < D_; d++) {
        float4 ev = *reinterpret_cast<const float4*>(&encs[d][lane * 4]);
        float2 ev01 = make_float2(ev.x, ev.y);
        float2 ev23 = make_float2(ev.z, ev.w);
        float4 wa = *reinterpret_cast<const float4*>(&Wt[d][e0]);
        float4 wb = *reinterpret_cast<const float4*>(&Wt[d][e0 + 4]);
        float wv[8] = {wa.x, wa.y, wa.z, wa.w, wb.x, wb.y, wb.z, wb.w};
#pragma unroll
        for (int e = 0; e < 8; e++) {
            float2 ee = make_float2(wv[e], wv[e]);
            ffma2(acc[e][0], ee, ev01);
            ffma2(acc[e][1], ee, ev23);
        }
    }
#pragma unroll
    for (int e = 0; e < 8; e++) {
        float bb = bias[e0 + e];
        float4 o = make_float4(acc[e][0].x + bb, acc[e][0].y + bb,
                               acc[e][1].x + bb, acc[e][1].y + bb);
        *reinterpret_cast<float4*>(
            &g_energyT[(((size_t)b * D_ + e0 + e) << 10) + jb * 128 + lane * 4]) = o;
    }
}

// ---------------------------------------------------------------------------
// Kernel 2: scores[t,b,j] = sum_k energyT[b][k][j] * enc[b][t][k]
//           cp.async double-buffered k-slabs, diag-zero, softmax (no max-sub),
//           write out[t][b][j].
// grid (32 tb, 32 b), 512 threads (16 warps). CTA tile: 32 t x 1024 j.
// warp = (tg = w>>2 : 8 t-rows, jq = w&3 : 256-j quarter).
// thread: 8 t-rows x 8 j (acc = 64 floats).
// ---------------------------------------------------------------------------
#define TPB 512
#define ES_FLOATS (2 * SLAB_K * 1024)
#define SMEM_FLOATS (ES_FLOATS + D_ * 36 + 4 * 32)
#define SMEM_BYTES (SMEM_FLOATS * 4)

__global__ __launch_bounds__(TPB, 1) void scores_kernel(
    const float* __restrict__ enc, float* __restrict__ out) {
    extern __shared__ float smem[];
    float* es   = smem;                      // [2][SLAB_K][1024]
    float* encs = smem + ES_FLOATS;          // [64][36]  (k-major, padded)
    float* sums = encs + D_ * 36;            // [4][32]

    const int b = blockIdx.y, tb = blockIdx.x, t0 = tb * 32;
    const int tid = threadIdx.x, w = tid >> 5, lane = tid & 31;
    const int tg = w >> 2, jq = w & 3;

    // enc tile (32 t x 64 k) transposed into smem [k][t] — 512 float4, 1/thread
    {
        const float4* enc4 =
            reinterpret_cast<const float4*>(enc + ((size_t)b * L_ + t0) * D_);
        int t = tid >> 4, dq = tid & 15;
        float4 v = enc4[tid];
        encs[(dq * 4 + 0) * 36 + t] = v.x; encs[(dq * 4 + 1) * 36 + t] = v.y;
        encs[(dq * 4 + 2) * 36 + t] = v.z; encs[(dq * 4 + 3) * 36 + t] = v.w;
    }

    const float* ebase = g_energyT + (size_t)b * D_ * L_;

    // prefetch slabs 0,1 (each 2048 x 16B chunks, 4/thread)
#pragma unroll
    for (int i = 0; i < 4; i++) {
        int c = tid + i * TPB;
        cp16(es + c * 4, ebase + c * 4);
    }
    cp_commit();
#pragma unroll
    for (int i = 0; i < 4; i++) {
        int c = tid + i * TPB;
        cp16(es + SLAB_K * 1024 + c * 4, ebase + SLAB_K * 1024 + c * 4);
    }
    cp_commit();

    float2 acc[8][4];   // [tt][m*2 + half]
#pragma unroll
    for (int tt = 0; tt < 8; tt++)
#pragma unroll
        for (int c = 0; c < 4; c++) acc[tt][c] = make_float2(0.f, 0.f);

    const int jbase = jq * 256 + lane * 4;   // thread's j cols: jbase, jbase+128

#pragma unroll 1
    for (int s = 0; s < NSLAB; s++) {
        cp_wait<1>();
        __syncthreads();
        const float* eb0 = es + (s & 1) * (SLAB_K * 1024) + jbase;
#pragma unroll
        for (int kk = 0; kk < SLAB_K; kk++) {
            const int k = s * SLAB_K + kk;
            const float* er = eb0 + kk * 1024;
            float4 g0 = *reinterpret_cast<const float4*>(er);
            float4 g1 = *reinterpret_cast<const float4*>(er + 128);
            float2 gl[4] = {make_float2(g0.x, g0.y), make_float2(g0.z, g0.w),
                            make_float2(g1.x, g1.y), make_float2(g1.z, g1.w)};
            float4 ea = *reinterpret_cast<const float4*>(&encs[k * 36 + tg * 8]);
            float4 eb = *reinterpret_cast<const float4*>(&encs[k * 36 + tg * 8 + 4]);
            float ev[8] = {ea.x, ea.y, ea.z, ea.w, eb.x, eb.y, eb.z, eb.w};
#pragma unroll
            for (int tt = 0; tt < 8; tt++) {
                float2 ee = make_float2(ev[tt], ev[tt]);
#pragma unroll
                for (int c = 0; c < 4; c++) ffma2(acc[tt][c], ee, gl[c]);
            }
        }
        __syncthreads();
        if (s + 2 < NSLAB) {
            const float* src = ebase + (size_t)(s + 2) * SLAB_K * 1024;
            float* dst = es + (s & 1) * (SLAB_K * 1024);
#pragma unroll
            for (int i = 0; i < 4; i++) {
                int c = tid + i * TPB;
                cp16(dst + c * 4, src + c * 4);
            }
        }
        cp_commit();
    }

    // ---- epilogue: diag zero + exp (no max-sub; |s| < ~45 so fp32-safe) ----
    float rs[8];
#pragma unroll
    for (int tt = 0; tt < 8; tt++) {
        const int t = t0 + tg * 8 + tt;
        float s = 0.f;
#pragma unroll
        for (int m = 0; m < 2; m++) {
            const int j4 = jbase + m * 128;
            float2* a0 = &acc[tt][2 * m];
            float2* a1 = &acc[tt][2 * m + 1];
            float v0 = (j4 + 0 == t) ? 0.f : a0->x;
            float v1 = (j4 + 1 == t) ? 0.f : a0->y;
            float v2 = (j4 + 2 == t) ? 0.f : a1->x;
            float v3 = (j4 + 3 == t) ? 0.f : a1->y;
            v0 = __expf(v0); v1 = __expf(v1); v2 = __expf(v2); v3 = __expf(v3);
            a0->x = v0; a0->y = v1; a1->x = v2; a1->y = v3;
            s += (v0 + v1) + (v2 + v3);
        }
#pragma unroll
        for (int o = 16; o > 0; o >>= 1)
            s += __shfl_xor_sync(0xffffffffu, s, o);
        rs[tt] = s;
    }
    if (lane == 0) {
#pragma unroll
        for (int tt = 0; tt < 8; tt++) sums[jq * 32 + tg * 8 + tt] = rs[tt];
    }
    __syncthreads();

    // ---- normalize + store ----
#pragma unroll
    for (int tt = 0; tt < 8; tt++) {
        const int lr = tg * 8 + tt;
        const float rinv =
            1.0f / (sums[lr] + sums[32 + lr] + sums[64 + lr] + sums[96 + lr]);
        float* orow = out + (((size_t)(t0 + lr) * B_ + b) << 10) + jbase;
#pragma unroll
        for (int m = 0; m < 2; m++) {
            float2 a0 = acc[tt][2 * m], a1 = acc[tt][2 * m + 1];
            *reinterpret_cast<float4*>(orow + m * 128) =
                make_float4(a0.x * rinv, a0.y * rinv, a1.x * rinv, a1.y * rinv);
        }
    }
}

extern "C" void kernel_launch(void* const* d_in, const int* in_sizes, int n_in,
                              void* d_out, int out_size) {
    (void)in_sizes; (void)n_in; (void)out_size;
    const float* enc  = (const float*)d_in[0];
    const float* W    = (const float*)d_in[1];
    const float* bias = (const float*)d_in[2];
    float* out = (float*)d_out;

    static int configured = 0;
    if (!configured) {
        cudaFuncSetAttribute(scores_kernel,
                             cudaFuncAttributeMaxDynamicSharedMemorySize, SMEM_BYTES);
        configured = 1;
    }

    energy_kernel<<<dim3(8, 32), 256>>>(enc, W, bias);
    scores_kernel<<<dim3(32, 32), TPB, SMEM_BYTES>>>(enc, out);
}

// round 6
// speedup vs baseline: 1.1762x; 1.0452x over previous
#include <cuda_runtime.h>
#include <cuda_bf16.h>
#include <cstdint>

#define B_ 32
#define L_ 1024
#define D_ 64

typedef __nv_bfloat16 bf16;

// energy bf16 hi/lo splits, [b][j][e] (e contiguous, 128B rows)
__device__ __align__(16) bf16 g_egy_hi[B_ * L_ * D_];
__device__ __align__(16) bf16 g_egy_lo[B_ * L_ * D_];

// ---------------------------------------------------------------------------
// helpers
// ---------------------------------------------------------------------------
__device__ __forceinline__ uint32_t smem_u32(const void* p) {
    uint32_t a;
    asm("{ .reg .u64 t; cvta.to.shared.u64 t, %1; cvt.u32.u64 %0, t; }"
        : "=r"(a) : "l"(p));
    return a;
}
__device__ __forceinline__ void cp16(void* dst_smem, const void* src) {
    uint32_t s = smem_u32(dst_smem);
    asm volatile("cp.async.cg.shared.global [%0], [%1], 16;" :: "r"(s), "l"(src));
}
__device__ __forceinline__ void cp_commit() { asm volatile("cp.async.commit_group;"); }
template <int N>
__device__ __forceinline__ void cp_wait() {
    asm volatile("cp.async.wait_group %0;" :: "n"(N));
}
__device__ __forceinline__ void ldsm_x4(uint32_t addr, uint32_t r[4]) {
    asm volatile("ldmatrix.sync.aligned.m8n8.x4.shared.b16 {%0,%1,%2,%3}, [%4];"
                 : "=r"(r[0]), "=r"(r[1]), "=r"(r[2]), "=r"(r[3]) : "r"(addr));
}
__device__ __forceinline__ void mma16816(float c[4], const uint32_t a[4],
                                         const uint32_t b0, const uint32_t b1) {
    asm volatile(
        "mma.sync.aligned.m16n8k16.row.col.f32.bf16.bf16.f32 "
        "{%0,%1,%2,%3}, {%4,%5,%6,%7}, {%8,%9}, {%0,%1,%2,%3};"
        : "+f"(c[0]), "+f"(c[1]), "+f"(c[2]), "+f"(c[3])
        : "r"(a[0]), "r"(a[1]), "r"(a[2]), "r"(a[3]), "r"(b0), "r"(b1));
}
__device__ __forceinline__ uint32_t swz(uint32_t o) { return o ^ ((o >> 3) & 0x70); }

__device__ __forceinline__ void split2(float a, float b, uint32_t& h, uint32_t& l) {
    bf16 ha = __float2bfloat16_rn(a), hb = __float2bfloat16_rn(b);
    bf16 la = __float2bfloat16_rn(a - __bfloat162float(ha));
    bf16 lb = __float2bfloat16_rn(b - __bfloat162float(hb));
    __nv_bfloat162 hh = __halves2bfloat162(ha, hb);
    __nv_bfloat162 ll = __halves2bfloat162(la, lb);
    h = *reinterpret_cast<uint32_t*>(&hh);
    l = *reinterpret_cast<uint32_t*>(&ll);
}

// ---------------------------------------------------------------------------
// Kernel 1: energy[b][j][e] = sum_d enc[b][j][d]*W[e][d] + bias[e] -> bf16 hi/lo
// grid (8 j-blocks, 32 b), 256 threads
// ---------------------------------------------------------------------------
__global__ __launch_bounds__(256) void energy_kernel(
    const float* __restrict__ enc, const float* __restrict__ W,
    const float* __restrict__ bias) {
    __shared__ float Wt[D_][D_];     // [d][e]
    __shared__ float encs[D_][128];  // [d][j]; reused as enT[e][j]
    const int b = blockIdx.y, jb = blockIdx.x;
    const int tid = threadIdx.x;

    const float4* W4 = reinterpret_cast<const float4*>(W);
#pragma unroll
    for (int i = 0; i < 4; i++) {
        int f = tid + i * 256;
        int e = f >> 4, dq = f & 15;
        float4 w = W4[f];
        Wt[dq * 4 + 0][e] = w.x; Wt[dq * 4 + 1][e] = w.y;
        Wt[dq * 4 + 2][e] = w.z; Wt[dq * 4 + 3][e] = w.w;
    }
    const float4* enc4 =
        reinterpret_cast<const float4*>(enc + ((size_t)b * L_ + (size_t)jb * 128) * D_);
#pragma unroll
    for (int i = 0; i < 8; i++) {
        int f = tid + i * 256;
        int j = f >> 4, dq = f & 15;
        float4 v = enc4[f];
        encs[dq * 4 + 0][j] = v.x; encs[dq * 4 + 1][j] = v.y;
        encs[dq * 4 + 2][j] = v.z; encs[dq * 4 + 3][j] = v.w;
    }
    __syncthreads();

    const int w = tid >> 5, lane = tid & 31;
    const int e0 = w * 8;
    float acc[8][4];
#pragma unroll
    for (int e = 0; e < 8; e++)
#pragma unroll
        for (int q = 0; q < 4; q++) acc[e][q] = 0.f;
#pragma unroll 4
    for (int d = 0; d < D_; d++) {
        float4 ev = *reinterpret_cast<const float4*>(&encs[d][lane * 4]);
        float4 wa = *reinterpret_cast<const float4*>(&Wt[d][e0]);
        float4 wb = *reinterpret_cast<const float4*>(&Wt[d][e0 + 4]);
        float wv[8] = {wa.x, wa.y, wa.z, wa.w, wb.x, wb.y, wb.z, wb.w};
#pragma unroll
        for (int e = 0; e < 8; e++) {
            acc[e][0] = fmaf(wv[e], ev.x, acc[e][0]);
            acc[e][1] = fmaf(wv[e], ev.y, acc[e][1]);
            acc[e][2] = fmaf(wv[e], ev.z, acc[e][2]);
            acc[e][3] = fmaf(wv[e], ev.w, acc[e][3]);
        }
    }
    __syncthreads();   // done reading encs as [d][j]
#pragma unroll
    for (int e = 0; e < 8; e++) {
        float bb = bias[e0 + e];
        float4 o = make_float4(acc[e][0] + bb, acc[e][1] + bb,
                               acc[e][2] + bb, acc[e][3] + bb);
        *reinterpret_cast<float4*>(&encs[e0 + e][lane * 4]) = o;  // enT[e][j]
    }
    __syncthreads();

    // emit bf16 hi/lo, layout [j][e]
    const int j = tid >> 1, eh = (tid & 1) * 32;
    const size_t row = (size_t)b * L_ + jb * 128 + j;
    uint32_t hp[16], lp[16];
#pragma unroll
    for (int k = 0; k < 16; k++) {
        float v0 = encs[eh + 2 * k][j];
        float v1 = encs[eh + 2 * k + 1][j];
        split2(v0, v1, hp[k], lp[k]);
    }
    uint4* dh = reinterpret_cast<uint4*>(g_egy_hi + row * D_ + eh);
    uint4* dl = reinterpret_cast<uint4*>(g_egy_lo + row * D_ + eh);
#pragma unroll
    for (int q = 0; q < 4; q++) {
        dh[q] = make_uint4(hp[4 * q], hp[4 * q + 1], hp[4 * q + 2], hp[4 * q + 3]);
        dl[q] = make_uint4(lp[4 * q], lp[4 * q + 1], lp[4 * q + 2], lp[4 * q + 3]);
    }
}

// ---------------------------------------------------------------------------
// Kernel 2: scores via mma.sync bf16-split x3, fused softmax.
// grid (32 tb, 32 b), 512 threads (16 warps). CTA: 32 t x 1024 j.
// warp w: mb = w&1 (m16 block), ng = w>>1 (n32 group per 256-j slab).
// acc[4 slabs][4 n8][4] = 64 f32/thread.
// A (enc rows t0..t0+31) split fp32->bf16 hi/lo in-kernel.
// B slabs (256 j x 64 e, hi+lo = 64KB) cp.async double-buffered.
// ---------------------------------------------------------------------------
#define A_HI 0
#define A_LO 4096
#define BB   8192
#define BUFSZ 65536
#define SUMS_OFF (BB + 2 * BUFSZ)
#define SMEM_TOTAL (SUMS_OFF + 8 * 32 * 4)

__global__ __launch_bounds__(512, 1) void scores_mma_kernel(
    const float* __restrict__ enc, float* __restrict__ out) {
    extern __shared__ char smem[];
    const uint32_t sb = smem_u32(smem);
    float* sums = reinterpret_cast<float*>(smem + SUMS_OFF);  // [8 ng][32 rows]

    const int tid = threadIdx.x, w = tid >> 5, lane = tid & 31;
    const int b = blockIdx.y, tb = blockIdx.x, t0 = tb * 32;
    const int mb = w & 1, ng = w >> 1;
    const int g = lane >> 2, qc = lane & 3;

    // ---- A: load enc fp32 tile (32 x 64), split to bf16 hi/lo smem ----
    {
        const float4* src =
            reinterpret_cast<const float4*>(enc + ((size_t)b * L_ + t0) * D_);
        float4 v = src[tid];                 // 512 float4 = whole tile
        int row = tid >> 4, c = tid & 15;    // k = c*4..c*4+3
        uint2 h, l;
        split2(v.x, v.y, h.x, l.x);
        split2(v.z, v.w, h.y, l.y);
        uint32_t off = swz(row * 128 + c * 8);
        *reinterpret_cast<uint2*>(smem + A_HI + off) = h;
        *reinterpret_cast<uint2*>(smem + A_LO + off) = l;
    }

    // ---- B slab loader ----
    const char* bhb = reinterpret_cast<const char*>(g_egy_hi + (size_t)b * L_ * D_);
    const char* blb = reinterpret_cast<const char*>(g_egy_lo + (size_t)b * L_ * D_);
    auto load_slab = [&](int s, int buf) {
        const char* sh = bhb + (size_t)s * 256 * 128;
        const char* sl = blb + (size_t)s * 256 * 128;
        char* dst = smem + BB + buf * BUFSZ;
#pragma unroll
        for (int i = 0; i < 8; i++) {
            int idx = tid + i * 512;          // 4096: 2 splits x 256 rows x 8
            int split = idx >> 11, rem = idx & 2047, row = rem >> 3, cc = rem & 7;
            cp16(dst + split * 32768 + swz(row * 128 + cc * 16),
                 (split ? sl : sh) + row * 128 + cc * 16);
        }
    };
    load_slab(0, 0); cp_commit();
    load_slab(1, 1); cp_commit();

    float acc[4][4][4];
#pragma unroll
    for (int s = 0; s < 4; s++)
#pragma unroll
        for (int nt = 0; nt < 4; nt++)
#pragma unroll
            for (int q = 0; q < 4; q++) acc[s][nt][q] = 0.f;

    const uint32_t a_row = (uint32_t)(mb * 16 + (lane & 15));
    const uint32_t a_kb = (uint32_t)((lane >> 4) * 8);
    const uint32_t b_rowoff = (uint32_t)(((lane >> 4) & 1) * 8 + (lane & 7));
    const uint32_t b_kb = (uint32_t)(((lane >> 3) & 1) * 8);

#pragma unroll 1
    for (int s = 0; s < 4; s++) {
        cp_wait<1>();
        __syncthreads();   // slab resident + (first iter) A split visible
        const uint32_t bbase = sb + BB + (s & 1) * BUFSZ;
#pragma unroll
        for (int ks = 0; ks < 4; ks++) {
            uint32_t ah[4], al[4];
            const uint32_t aoff = swz(a_row * 128 + (a_kb + ks * 16) * 2);
            ldsm_x4(sb + A_HI + aoff, ah);
            ldsm_x4(sb + A_LO + aoff, al);
#pragma unroll
            for (int np = 0; np < 2; np++) {
                const uint32_t boff =
                    swz((ng * 32 + np * 16 + b_rowoff) * 128 + (b_kb + ks * 16) * 2);
                uint32_t bh[4], bl[4];
                ldsm_x4(bbase + boff, bh);
                ldsm_x4(bbase + 32768 + boff, bl);
                float* A0 = acc[s][np * 2];
                float* A1 = acc[s][np * 2 + 1];
                mma16816(A0, ah, bh[0], bh[1]);
                mma16816(A1, ah, bh[2], bh[3]);
                mma16816(A0, al, bh[0], bh[1]);
                mma16816(A1, al, bh[2], bh[3]);
                mma16816(A0, ah, bl[0], bl[1]);
                mma16816(A1, ah, bl[2], bl[3]);
            }
        }
        __syncthreads();
        if (s + 2 < 4) load_slab(s + 2, s & 1);
        cp_commit();
    }

    // ---- epilogue: diag zero, exp (no max-sub: |s|<~45, fp32-safe), sums ----
    const int r0 = t0 + mb * 16 + g;
    const int r1 = r0 + 8;
    float s0 = 0.f, s1 = 0.f;
#pragma unroll
    for (int s = 0; s < 4; s++)
#pragma unroll
        for (int nt = 0; nt < 4; nt++) {
            const int j = s * 256 + ng * 32 + nt * 8 + qc * 2;
            float* a = acc[s][nt];
            float v0 = (j == r0) ? 0.f : a[0];
            float v1 = (j + 1 == r0) ? 0.f : a[1];
            float v2 = (j == r1) ? 0.f : a[2];
            float v3 = (j + 1 == r1) ? 0.f : a[3];
            v0 = __expf(v0); v1 = __expf(v1); v2 = __expf(v2); v3 = __expf(v3);
            a[0] = v0; a[1] = v1; a[2] = v2; a[3] = v3;
            s0 += v0 + v1; s1 += v2 + v3;
        }
#pragma unroll
    for (int o = 1; o < 4; o <<= 1) {
        s0 += __shfl_xor_sync(0xffffffffu, s0, o);
        s1 += __shfl_xor_sync(0xffffffffu, s1, o);
    }
    if (qc == 0) {
        sums[ng * 32 + mb * 16 + g] = s0;
        sums[ng * 32 + mb * 16 + g + 8] = s1;
    }
    __syncthreads();
    const int lr0 = mb * 16 + g, lr1 = lr0 + 8;
    float tot0 = 0.f, tot1 = 0.f;
#pragma unroll
    for (int q = 0; q < 8; q++) {
        tot0 += sums[q * 32 + lr0];
        tot1 += sums[q * 32 + lr1];
    }
    const float rinv0 = 1.0f / tot0, rinv1 = 1.0f / tot1;

    // ---- normalize + store out[t][b][j] ----
    float* out0 = out + (((size_t)r0 * B_ + b) << 10);
    float* out1 = out + (((size_t)r1 * B_ + b) << 10);
#pragma unroll
    for (int s = 0; s < 4; s++)
#pragma unroll
        for (int nt = 0; nt < 4; nt++) {
            const int j = s * 256 + ng * 32 + nt * 8 + qc * 2;
            float* a = acc[s][nt];
            *reinterpret_cast<float2*>(out0 + j) =
                make_float2(a[0] * rinv0, a[1] * rinv0);
            *reinterpret_cast<float2*>(out1 + j) =
                make_float2(a[2] * rinv1, a[3] * rinv1);
        }
}

// ---------------------------------------------------------------------------
extern "C" void kernel_launch(void* const* d_in, const int* in_sizes, int n_in,
                              void* d_out, int out_size) {
    (void)in_sizes; (void)n_in; (void)out_size;
    const float* enc  = (const float*)d_in[0];
    const float* W    = (const float*)d_in[1];
    const float* bias = (const float*)d_in[2];
    float* out = (float*)d_out;

    static int configured = 0;
    if (!configured) {
        cudaFuncSetAttribute(scores_mma_kernel,
                             cudaFuncAttributeMaxDynamicSharedMemorySize, SMEM_TOTAL);
        configured = 1;
    }

    energy_kernel<<<dim3(8, 32), 256>>>(enc, W, bias);
    scores_mma_kernel<<<dim3(32, 32), 512, SMEM_TOTAL>>>(enc, out);
}